// round 14
// baseline (speedup 1.0000x reference)
#include <cuda_runtime.h>
#include <cuda_bf16.h>
#include <math.h>
#include <stdint.h>

#define BB 2
#define TT 2048
#define NH 16
#define HD 64
#define DD 1024
#define D3 3072
#define BT 4096   // BB*TT

// ---------------------------------------------------------------------------
// Scratch (no allocations allowed)
// ---------------------------------------------------------------------------
__device__ __nv_bfloat16 g_x_hi [(size_t)BT * DD];
__device__ __nv_bfloat16 g_x_lo [(size_t)BT * DD];
__device__ __nv_bfloat16 g_c_hi [(size_t)BT * DD];
__device__ __nv_bfloat16 g_c_lo [(size_t)BT * DD];
__device__ __nv_bfloat16 g_q_hi [(size_t)BT * DD];
__device__ __nv_bfloat16 g_q_lo [(size_t)BT * DD];
__device__ __nv_bfloat16 g_k_hi [(size_t)BT * DD];
__device__ __nv_bfloat16 g_k_lo [(size_t)BT * DD];
__device__ __nv_bfloat16 g_v_hi [(size_t)BT * DD];
__device__ __nv_bfloat16 g_v_lo [(size_t)BT * DD];
__device__ __nv_bfloat16 g_wq_hi[(size_t)D3 * DD];   // Wqkv^T
__device__ __nv_bfloat16 g_wq_lo[(size_t)D3 * DD];
__device__ __nv_bfloat16 g_wo_hi[(size_t)DD * DD];   // Wout^T
__device__ __nv_bfloat16 g_wo_lo[(size_t)DD * DD];
__device__ float2 g_rtab[TT * 32];                   // cos/sin table

// ---------------------------------------------------------------------------
__device__ __forceinline__ uint32_t smem_u32(const void* p) {
    uint32_t a;
    asm("{ .reg .u64 t; cvta.to.shared.u64 t, %1; cvt.u32.u64 %0, t; }"
        : "=r"(a) : "l"(p));
    return a;
}
__device__ __forceinline__ void bf16_split(float v, __nv_bfloat16& h, __nv_bfloat16& l) {
    h = __float2bfloat16_rn(v);
    l = __float2bfloat16_rn(v - __bfloat162float(h));
}
__device__ __forceinline__ void cp16(uint32_t dst, const void* src) {
    asm volatile("cp.async.ca.shared.global [%0], [%1], 16;" :: "r"(dst), "l"(src));
}
__device__ __forceinline__ void cp_commit() {
    asm volatile("cp.async.commit_group;" ::: "memory");
}
__device__ __forceinline__ void cp_wait0() {
    asm volatile("cp.async.wait_group 0;" ::: "memory");
}
__device__ __forceinline__ void cp_wait1() {
    asm volatile("cp.async.wait_group 1;" ::: "memory");
}
__device__ __forceinline__ void ldm_x4(uint32_t* r, uint32_t addr) {
    asm volatile("ldmatrix.sync.aligned.m8n8.x4.shared.b16 {%0,%1,%2,%3}, [%4];"
                 : "=r"(r[0]), "=r"(r[1]), "=r"(r[2]), "=r"(r[3]) : "r"(addr));
}
__device__ __forceinline__ void ldm_x4t(uint32_t* r, uint32_t addr) {
    asm volatile("ldmatrix.sync.aligned.m8n8.x4.trans.shared.b16 {%0,%1,%2,%3}, [%4];"
                 : "=r"(r[0]), "=r"(r[1]), "=r"(r[2]), "=r"(r[3]) : "r"(addr));
}
__device__ __forceinline__ void mma16816(float* c, const uint32_t* a, const uint32_t* b) {
    asm volatile(
        "mma.sync.aligned.m16n8k16.row.col.f32.bf16.bf16.f32 "
        "{%0,%1,%2,%3}, {%4,%5,%6,%7}, {%8,%9}, {%0,%1,%2,%3};"
        : "+f"(c[0]), "+f"(c[1]), "+f"(c[2]), "+f"(c[3])
        : "r"(a[0]), "r"(a[1]), "r"(a[2]), "r"(a[3]), "r"(b[0]), "r"(b[1]));
}
__device__ __forceinline__ uint32_t pack_bf16(float lo, float hi) {
    uint32_t r;
    asm("cvt.rn.bf16x2.f32 %0, %1, %2;" : "=r"(r) : "f"(hi), "f"(lo));
    return r;
}
// split pair (a,b) into hi bf16x2 + residual-lo bf16x2 (a in low half)
__device__ __forceinline__ void split2(float a, float b, uint32_t& hi, uint32_t& lo) {
    hi = pack_bf16(a, b);
    float ra = a - __uint_as_float(hi << 16);
    float rb = b - __uint_as_float(hi & 0xffff0000u);
    lo = pack_bf16(ra, rb);
}
// Conflict-free tile offset: 128 rows x 32 k bf16, row pairs packed in 128B
__device__ __forceinline__ uint32_t toff(int row, int c) {
    const int phys = row >> 1;
    const int unit = ((row & 1) * 4 + c) ^ (phys & 3);
    return (uint32_t)(phys * 128 + unit * 16);
}

// ---------------------------------------------------------------------------
// Elementwise fp32 -> bf16 hi/lo split
// ---------------------------------------------------------------------------
__global__ __launch_bounds__(256) void split_bf16(
    const float* __restrict__ src, __nv_bfloat16* __restrict__ hi,
    __nv_bfloat16* __restrict__ lo, int n4)
{
    int i = blockIdx.x * blockDim.x + threadIdx.x;
    if (i >= n4) return;
    float4 v = *(const float4*)(src + (size_t)i * 4);
    __nv_bfloat16 h[4], l[4];
    bf16_split(v.x, h[0], l[0]);
    bf16_split(v.y, h[1], l[1]);
    bf16_split(v.z, h[2], l[2]);
    bf16_split(v.w, h[3], l[3]);
    *(uint64_t*)(hi + (size_t)i * 4) = *(uint64_t*)h;
    *(uint64_t*)(lo + (size_t)i * 4) = *(uint64_t*)l;
}

// ---------------------------------------------------------------------------
// Transpose + bf16 split: W[K][N] -> Thi/Tlo[N][K] bf16
// ---------------------------------------------------------------------------
__global__ __launch_bounds__(256) void transpose_split(
    const float* __restrict__ W, __nv_bfloat16* __restrict__ Thi,
    __nv_bfloat16* __restrict__ Tlo, int K, int N)
{
    __shared__ float t[32][33];
    const int nb = blockIdx.x * 32, kb = blockIdx.y * 32;
    const int tx = threadIdx.x & 31, ty0 = threadIdx.x >> 5;
#pragma unroll
    for (int i = 0; i < 4; i++) {
        int row = ty0 + i * 8;
        t[row][tx] = W[(size_t)(kb + row) * N + nb + tx];
    }
    __syncthreads();
#pragma unroll
    for (int i = 0; i < 4; i++) {
        int row = ty0 + i * 8;
        float v = t[tx][row];
        __nv_bfloat16 h, l;
        bf16_split(v, h, l);
        size_t o = (size_t)(nb + row) * K + kb + tx;
        Thi[o] = h;
        Tlo[o] = l;
    }
}

// ---------------------------------------------------------------------------
// RoPE cos/sin table: tab[t*32 + i] = (cos, sin)((t+off) * invfreq_i)
// ---------------------------------------------------------------------------
__global__ __launch_bounds__(256) void build_rope(
    float2* __restrict__ tab, const int* __restrict__ offp)
{
    int idx = blockIdx.x * blockDim.x + threadIdx.x;   // 65536
    int i = idx & 31, t = idx >> 5;
    int off = offp ? offp[0] : 0;
    float invf = exp2f(-(float)(2 * i) * (0.015625f * 13.287712379549449f));
    float s, c;
    sincosf((float)(t + off) * invf, &s, &c);
    tab[idx] = make_float2(c, s);
}

// ---------------------------------------------------------------------------
// bf16-split GEMM via mma.sync; 2-stage cp.async, paired ldmatrix.x4 B,
// hoisted LDSM offsets. Template ROPE: fused rope/split epilogue for QKV.
// ---------------------------------------------------------------------------
#define GSMEM (2 * 32768)

template<bool ROPE>
__global__ __launch_bounds__(256, 2) void gemm_bf16_t(
    const __nv_bfloat16* __restrict__ Ahi, const __nv_bfloat16* __restrict__ Alo,
    const __nv_bfloat16* __restrict__ Bhi, const __nv_bfloat16* __restrict__ Blo,
    const float* __restrict__ bias, float* __restrict__ C,
    const float2* __restrict__ rtab, float* __restrict__ cache,
    __nv_bfloat16* __restrict__ qh, __nv_bfloat16* __restrict__ ql,
    __nv_bfloat16* __restrict__ kh, __nv_bfloat16* __restrict__ kl,
    __nv_bfloat16* __restrict__ vh, __nv_bfloat16* __restrict__ vl,
    int M, int N, int K)
{
    extern __shared__ char sm[];
    const uint32_t sB = smem_u32(sm);
    const int tid = threadIdx.x, wid = tid >> 5, lane = tid & 31;
    const int bn = blockIdx.x, bm = blockIdx.y;
    const int wm = wid & 1, wn = wid >> 1;
    const int NC = K >> 5;

    const __nv_bfloat16* gbase[4];
    gbase[0] = Ahi + (size_t)bm * 128 * K;
    gbase[1] = Alo + (size_t)bm * 128 * K;
    gbase[2] = Bhi + (size_t)bn * 128 * K;
    gbase[3] = Blo + (size_t)bn * 128 * K;

    auto load_chunk = [&](int c, int s) {
#pragma unroll
        for (int t = 0; t < 8; t++) {
            int id = tid + t * 256;
            int tile = id >> 9;
            int rem = id & 511;
            int row = rem >> 2, ch = rem & 3;
            const __nv_bfloat16* src = gbase[tile] + (size_t)row * K + c * 32 + ch * 8;
            uint32_t dst = sB + s * 32768 + tile * 8192 + toff(row, ch);
            cp16(dst, src);
        }
    };

    float acc[4][4][4];
#pragma unroll
    for (int i = 0; i < 4; i++)
#pragma unroll
        for (int j = 0; j < 4; j++)
#pragma unroll
            for (int k = 0; k < 4; k++) acc[i][j][k] = 0.f;

    const int l15 = lane & 15, lhi = lane >> 4;
    const int b7 = lane & 7, bK = (lane >> 3) & 1;

    // hoisted LDSM offsets (loop-invariant across chunks)
    uint32_t aOffH[2][4], bOffH[2][2];
#pragma unroll
    for (int ks = 0; ks < 2; ks++) {
#pragma unroll
        for (int mt = 0; mt < 4; mt++)
            aOffH[ks][mt] = toff(wm * 64 + mt * 16 + l15, ks * 2 + lhi);
#pragma unroll
        for (int p = 0; p < 2; p++)
            bOffH[ks][p] = toff(wn * 32 + (2 * p + lhi) * 8 + b7, ks * 2 + bK);
    }

    load_chunk(0, 0);
    cp_commit();

    for (int c = 0; c < NC; c++) {
        const int s = c & 1;
        if (c + 1 < NC) {
            load_chunk(c + 1, s ^ 1);
            cp_commit();
            cp_wait1();
        } else {
            cp_wait0();
        }
        __syncthreads();

        const uint32_t base = sB + s * 32768;
        const uint32_t aHiT = base, aLoT = base + 8192;
        const uint32_t bHiT = base + 16384, bLoT = base + 24576;

#pragma unroll
        for (int ks = 0; ks < 2; ks++) {
            uint32_t aF[4][4], bF[4][2], bF2[4][2];
#pragma unroll
            for (int mt = 0; mt < 4; mt++) ldm_x4(aF[mt], aHiT + aOffH[ks][mt]);
#pragma unroll
            for (int p = 0; p < 2; p++) {
                uint32_t t4[4];
                ldm_x4(t4, bHiT + bOffH[ks][p]);
                bF[2 * p][0] = t4[0]; bF[2 * p][1] = t4[1];
                bF[2 * p + 1][0] = t4[2]; bF[2 * p + 1][1] = t4[3];
            }
#pragma unroll
            for (int mt = 0; mt < 4; mt++)
#pragma unroll
                for (int nt = 0; nt < 4; nt++)
                    mma16816(acc[mt][nt], aF[mt], bF[nt]);
#pragma unroll
            for (int p = 0; p < 2; p++) {
                uint32_t t4[4];
                ldm_x4(t4, bLoT + bOffH[ks][p]);
                bF2[2 * p][0] = t4[0]; bF2[2 * p][1] = t4[1];
                bF2[2 * p + 1][0] = t4[2]; bF2[2 * p + 1][1] = t4[3];
            }
#pragma unroll
            for (int mt = 0; mt < 4; mt++)
#pragma unroll
                for (int nt = 0; nt < 4; nt++)
                    mma16816(acc[mt][nt], aF[mt], bF2[nt]);
#pragma unroll
            for (int mt = 0; mt < 4; mt++) ldm_x4(aF[mt], aLoT + aOffH[ks][mt]);
#pragma unroll
            for (int mt = 0; mt < 4; mt++)
#pragma unroll
                for (int nt = 0; nt < 4; nt++)
                    mma16816(acc[mt][nt], aF[mt], bF[nt]);
        }
        __syncthreads();
    }

    const int g = lane >> 2, tg2 = (lane & 3) * 2;

    if (!ROPE) {
#pragma unroll
        for (int nt = 0; nt < 4; nt++) {
            const int col = bn * 128 + wn * 32 + nt * 8 + tg2;
            const float b0 = bias[col], b1 = bias[col + 1];
#pragma unroll
            for (int mt = 0; mt < 4; mt++) {
                const int r0 = bm * 128 + wm * 64 + mt * 16 + g;
                float2 v0 = make_float2(acc[mt][nt][0] + b0, acc[mt][nt][1] + b1);
                float2 v1 = make_float2(acc[mt][nt][2] + b0, acc[mt][nt][3] + b1);
                *(float2*)(C + (size_t)r0 * N + col) = v0;
                *(float2*)(C + (size_t)(r0 + 8) * N + col) = v1;
            }
        }
    } else {
        // fused rope/split epilogue: N = 3072, col type uniform per CTA
        const int type = (bn * 128) >> 10;   // 0=q, 1=k, 2=v
#pragma unroll
        for (int nt = 0; nt < 4; nt++) {
            const int col = bn * 128 + wn * 32 + nt * 8 + tg2;
            const int lcol = col & 1023;
            const int ri = (col & 63) >> 1;
            const float b0 = bias[col], b1 = bias[col + 1];
#pragma unroll
            for (int mt = 0; mt < 4; mt++) {
                const int r0 = bm * 128 + wm * 64 + mt * 16 + g;
#pragma unroll
                for (int half = 0; half < 2; half++) {
                    const int rr = r0 + half * 8;
                    const int t = rr & (TT - 1), bb = rr >> 11;
                    float x1 = acc[mt][nt][2 * half] + b0;
                    float x2 = acc[mt][nt][2 * half + 1] + b1;
                    uint32_t hi, lo;
                    if (type == 2) {
                        size_t co = ((size_t)((bb * 2 + 1) * TT + t)) * DD + lcol;
                        cache[co] = x1;
                        cache[co + 1] = x2;
                        split2(x1, x2, hi, lo);
                        *(uint32_t*)(vh + (size_t)rr * DD + lcol) = hi;
                        *(uint32_t*)(vl + (size_t)rr * DD + lcol) = lo;
                    } else {
                        float2 cs = rtab[t * 32 + ri];
                        float y1 = x1 * cs.x - x2 * cs.y;
                        float y2 = x1 * cs.y + x2 * cs.x;
                        if (type == 0) {
                            split2(y1 * 0.125f, y2 * 0.125f, hi, lo);
                            *(uint32_t*)(qh + (size_t)rr * DD + lcol) = hi;
                            *(uint32_t*)(ql + (size_t)rr * DD + lcol) = lo;
                        } else {
                            size_t co = ((size_t)((bb * 2) * TT + t)) * DD + lcol;
                            cache[co] = y1;
                            cache[co + 1] = y2;
                            split2(y1, y2, hi, lo);
                            *(uint32_t*)(kh + (size_t)rr * DD + lcol) = hi;
                            *(uint32_t*)(kl + (size_t)rr * DD + lcol) = lo;
                        }
                    }
                }
            }
        }
    }
}

// ---------------------------------------------------------------------------
// Tensor-core flash attention (unchanged from R13).
// ---------------------------------------------------------------------------
#define APITCH 72
#define QREG  (128 * APITCH * 2)
#define KVARR (64 * APITCH * 2)
#define KVST  (4 * KVARR)
#define ATT_SMEM (2 * QREG + 2 * KVST)

__global__ __launch_bounds__(256, 2) void attn_mma(
    const __nv_bfloat16* __restrict__ qh, const __nv_bfloat16* __restrict__ ql,
    const __nv_bfloat16* __restrict__ kh, const __nv_bfloat16* __restrict__ kl,
    const __nv_bfloat16* __restrict__ vh, const __nv_bfloat16* __restrict__ vl,
    __nv_bfloat16* __restrict__ ch, __nv_bfloat16* __restrict__ cl)
{
    extern __shared__ char smc[];
    const uint32_t sbase = smem_u32(smc);
    const uint32_t sQH = sbase, sQL = sbase + QREG;

    const int tid = threadIdx.x, wid = tid >> 5, lane = tid & 31;
    const int px = blockIdx.x, bh = blockIdx.y;
    const int b = bh >> 4, h = bh & 15;
    const int l15 = lane & 15, lhi = lane >> 4;
    const int g = lane >> 2, tg2 = (lane & 3) * 2;
    const int b7 = lane & 7, bK = (lane >> 3) & 1;

    const size_t hoff = ((size_t)(b * TT)) * DD + h * HD;
    const __nv_bfloat16* qhb = qh + hoff;
    const __nv_bfloat16* qlb = ql + hoff;
    const __nv_bfloat16* srcs[4] = {kh + hoff, kl + hoff, vh + hoff, vl + hoff};

    auto load_q = [&](int mblk) {
#pragma unroll
        for (int t = 0; t < 8; t++) {
            int id = tid + t * 256;
            int arr = id >> 10;
            int rem = id & 1023;
            int r = rem >> 3, chk = rem & 7;
            const __nv_bfloat16* src =
                (arr ? qlb : qhb) + (size_t)(mblk * 128 + r) * DD + chk * 8;
            uint32_t dst = (arr ? sQL : sQH) + r * 144 + chk * 16;
            cp16(dst, src);
        }
    };
    auto load_kv = [&](int kb, int stg) {
        const uint32_t kvb = sbase + 2 * QREG + stg * KVST;
#pragma unroll
        for (int t = 0; t < 8; t++) {
            int id = tid + t * 256;
            int arr = id >> 9;
            int rem = id & 511;
            int r = rem >> 3, chk = rem & 7;
            const __nv_bfloat16* src = srcs[arr] + (size_t)(kb * 64 + r) * DD + chk * 8;
            uint32_t dst = kvb + arr * KVARR + r * 144 + chk * 16;
            cp16(dst, src);
        }
    };

    for (int pass = 0; pass < 2; pass++) {
        const int mblk = pass ? (15 - px) : px;
        const int NKT = 2 * mblk + 2;

        __syncthreads();
        load_q(mblk);
        load_kv(0, 0);
        cp_commit();

        float o[8][4];
#pragma unroll
        for (int i = 0; i < 8; i++)
#pragma unroll
            for (int j = 0; j < 4; j++) o[i][j] = 0.f;
        float m0 = -1e30f, m1 = -1e30f, l0 = 0.f, l1 = 0.f;

        const int rowA = mblk * 128 + wid * 16 + g;
        const uint32_t aRowOff = (wid * 16 + l15) * 144;

        for (int kb = 0; kb < NKT; kb++) {
            const int stg = kb & 1;
            __syncthreads();
            if (kb + 1 < NKT) {
                load_kv(kb + 1, stg ^ 1);
                cp_commit();
                cp_wait1();
            } else {
                cp_wait0();
            }
            __syncthreads();

            const uint32_t kvb = sbase + 2 * QREG + stg * KVST;
            const uint32_t sKH = kvb, sKL = kvb + KVARR;
            const uint32_t sVH = kvb + 2 * KVARR, sVL = kvb + 3 * KVARR;

            float s[8][4];
#pragma unroll
            for (int i = 0; i < 8; i++)
#pragma unroll
                for (int j = 0; j < 4; j++) s[i][j] = 0.f;

#pragma unroll
            for (int ks = 0; ks < 4; ks++) {
                const uint32_t ach = (uint32_t)((ks * 2 + lhi) << 4);
                uint32_t aH[4], aL[4];
                ldm_x4(aH, sQH + aRowOff + ach);
                ldm_x4(aL, sQL + aRowOff + ach);
                const uint32_t bch = (uint32_t)((ks * 2 + bK) << 4);
#pragma unroll
                for (int p = 0; p < 4; p++) {
                    const uint32_t bro = ((2 * p + lhi) * 8 + b7) * 144 + bch;
                    uint32_t tH[4], tL[4];
                    ldm_x4(tH, sKH + bro);
                    ldm_x4(tL, sKL + bro);
                    mma16816(s[2 * p],     aH, &tH[0]);
                    mma16816(s[2 * p],     aH, &tL[0]);
                    mma16816(s[2 * p],     aL, &tH[0]);
                    mma16816(s[2 * p + 1], aH, &tH[2]);
                    mma16816(s[2 * p + 1], aH, &tL[2]);
                    mma16816(s[2 * p + 1], aL, &tH[2]);
                }
            }

            if (kb >= 2 * mblk) {
                const int cbase = kb * 64;
#pragma unroll
                for (int nt = 0; nt < 8; nt++) {
                    const int c0 = cbase + nt * 8 + tg2;
                    if (c0 > rowA)     s[nt][0] = -1e30f;
                    if (c0 + 1 > rowA) s[nt][1] = -1e30f;
                    if (c0 > rowA + 8)     s[nt][2] = -1e30f;
                    if (c0 + 1 > rowA + 8) s[nt][3] = -1e30f;
                }
            }

            float mx0 = -1e30f, mx1 = -1e30f;
#pragma unroll
            for (int nt = 0; nt < 8; nt++) {
                mx0 = fmaxf(mx0, fmaxf(s[nt][0], s[nt][1]));
                mx1 = fmaxf(mx1, fmaxf(s[nt][2], s[nt][3]));
            }
            mx0 = fmaxf(mx0, __shfl_xor_sync(0xffffffffu, mx0, 1));
            mx0 = fmaxf(mx0, __shfl_xor_sync(0xffffffffu, mx0, 2));
            mx1 = fmaxf(mx1, __shfl_xor_sync(0xffffffffu, mx1, 1));
            mx1 = fmaxf(mx1, __shfl_xor_sync(0xffffffffu, mx1, 2));
            const float mn0 = fmaxf(m0, mx0), mn1 = fmaxf(m1, mx1);
            const float al0 = __expf(m0 - mn0), al1 = __expf(m1 - mn1);
            m0 = mn0; m1 = mn1;
            float sum0 = 0.f, sum1 = 0.f;
#pragma unroll
            for (int nt = 0; nt < 8; nt++) {
                s[nt][0] = __expf(s[nt][0] - mn0);
                s[nt][1] = __expf(s[nt][1] - mn0);
                s[nt][2] = __expf(s[nt][2] - mn1);
                s[nt][3] = __expf(s[nt][3] - mn1);
                sum0 += s[nt][0] + s[nt][1];
                sum1 += s[nt][2] + s[nt][3];
            }
            sum0 += __shfl_xor_sync(0xffffffffu, sum0, 1);
            sum0 += __shfl_xor_sync(0xffffffffu, sum0, 2);
            sum1 += __shfl_xor_sync(0xffffffffu, sum1, 1);
            sum1 += __shfl_xor_sync(0xffffffffu, sum1, 2);
            l0 = l0 * al0 + sum0;
            l1 = l1 * al1 + sum1;
#pragma unroll
            for (int nt = 0; nt < 8; nt++) {
                o[nt][0] *= al0; o[nt][1] *= al0;
                o[nt][2] *= al1; o[nt][3] *= al1;
            }

#pragma unroll
            for (int kt = 0; kt < 4; kt++) {
                const int n0 = kt * 2, n1 = kt * 2 + 1;
                uint32_t pH[4], pL[4];
                split2(s[n0][0], s[n0][1], pH[0], pL[0]);
                split2(s[n0][2], s[n0][3], pH[1], pL[1]);
                split2(s[n1][0], s[n1][1], pH[2], pL[2]);
                split2(s[n1][2], s[n1][3], pH[3], pL[3]);
#pragma unroll
                for (int p = 0; p < 4; p++) {
                    const uint32_t va = (kt * 16 + l15) * 144 + (2 * p + lhi) * 16;
                    uint32_t tH[4], tL[4];
                    ldm_x4t(tH, sVH + va);
                    ldm_x4t(tL, sVL + va);
                    mma16816(o[2 * p],     pH, &tH[0]);
                    mma16816(o[2 * p],     pH, &tL[0]);
                    mma16816(o[2 * p],     pL, &tH[0]);
                    mma16816(o[2 * p + 1], pH, &tH[2]);
                    mma16816(o[2 * p + 1], pH, &tL[2]);
                    mma16816(o[2 * p + 1], pL, &tH[2]);
                }
            }
        }

        const float inv0 = 1.f / l0, inv1 = 1.f / l1;
        __nv_bfloat16* ch0 = ch + (size_t)(b * TT + rowA) * DD + h * HD;
        __nv_bfloat16* cl0 = cl + (size_t)(b * TT + rowA) * DD + h * HD;
        __nv_bfloat16* ch1 = ch0 + (size_t)8 * DD;
        __nv_bfloat16* cl1 = cl0 + (size_t)8 * DD;
#pragma unroll
        for (int nt = 0; nt < 8; nt++) {
            uint32_t hi, lo;
            split2(o[nt][0] * inv0, o[nt][1] * inv0, hi, lo);
            *(uint32_t*)(ch0 + nt * 8 + tg2) = hi;
            *(uint32_t*)(cl0 + nt * 8 + tg2) = lo;
            split2(o[nt][2] * inv1, o[nt][3] * inv1, hi, lo);
            *(uint32_t*)(ch1 + nt * 8 + tg2) = hi;
            *(uint32_t*)(cl1 + nt * 8 + tg2) = lo;
        }
    }
}

// ---------------------------------------------------------------------------
extern "C" void kernel_launch(void* const* d_in, const int* in_sizes, int n_in,
                              void* d_out, int out_size)
{
    const float* x    = (const float*)d_in[0];
    const float* Wqkv = (const float*)d_in[1];
    const float* bqkv = (const float*)d_in[2];
    const float* Wout = (const float*)d_in[3];
    const float* bout = (const float*)d_in[4];
    const int*   offp = (n_in > 5) ? (const int*)d_in[5] : nullptr;

    float* out   = (float*)d_out;
    float* cache = out + (size_t)BT * DD;

    __nv_bfloat16 *xh, *xl, *ch, *cl, *wqh, *wql, *woh, *wol;
    __nv_bfloat16 *qh, *ql, *kh, *kl, *vh, *vl;
    float2* rtab;
    cudaGetSymbolAddress((void**)&xh,   g_x_hi);
    cudaGetSymbolAddress((void**)&xl,   g_x_lo);
    cudaGetSymbolAddress((void**)&ch,   g_c_hi);
    cudaGetSymbolAddress((void**)&cl,   g_c_lo);
    cudaGetSymbolAddress((void**)&wqh,  g_wq_hi);
    cudaGetSymbolAddress((void**)&wql,  g_wq_lo);
    cudaGetSymbolAddress((void**)&woh,  g_wo_hi);
    cudaGetSymbolAddress((void**)&wol,  g_wo_lo);
    cudaGetSymbolAddress((void**)&qh,   g_q_hi);
    cudaGetSymbolAddress((void**)&ql,   g_q_lo);
    cudaGetSymbolAddress((void**)&kh,   g_k_hi);
    cudaGetSymbolAddress((void**)&kl,   g_k_lo);
    cudaGetSymbolAddress((void**)&vh,   g_v_hi);
    cudaGetSymbolAddress((void**)&vl,   g_v_lo);
    cudaGetSymbolAddress((void**)&rtab, g_rtab);

    cudaFuncSetAttribute(gemm_bf16_t<true>,
                         cudaFuncAttributeMaxDynamicSharedMemorySize, GSMEM);
    cudaFuncSetAttribute(gemm_bf16_t<false>,
                         cudaFuncAttributeMaxDynamicSharedMemorySize, GSMEM);
    cudaFuncSetAttribute(attn_mma, cudaFuncAttributeMaxDynamicSharedMemorySize,
                         ATT_SMEM);

    // 0) input split, weight transpose+split, rope table
    split_bf16<<<(BT * DD / 4) / 256, 256>>>(x, xh, xl, BT * DD / 4);
    transpose_split<<<dim3(D3 / 32, DD / 32), 256>>>(Wqkv, wqh, wql, DD, D3);
    transpose_split<<<dim3(DD / 32, DD / 32), 256>>>(Wout, woh, wol, DD, DD);
    build_rope<<<(TT * 32) / 256, 256>>>(rtab, offp);

    // 1) QKV projection + fused rope/scatter/split epilogue
    gemm_bf16_t<true><<<dim3(D3 / 128, BT / 128), 256, GSMEM>>>(
        xh, xl, wqh, wql, bqkv, nullptr, rtab, cache,
        qh, ql, kh, kl, vh, vl, BT, D3, DD);

    // 2) Tensor-core causal flash attention (writes ctx as bf16 hi/lo)
    attn_mma<<<dim3(8, BB * NH), 256, ATT_SMEM>>>(
        qh, ql, kh, kl, vh, vl, ch, cl);

    // 3) Output projection
    gemm_bf16_t<false><<<dim3(DD / 128, BT / 128), 256, GSMEM>>>(
        ch, cl, woh, wol, bout, out, nullptr, nullptr,
        nullptr, nullptr, nullptr, nullptr, nullptr, nullptr, BT, DD, DD);
}

// round 15
// speedup vs baseline: 1.4134x; 1.4134x over previous
#include <cuda_runtime.h>
#include <cuda_fp16.h>
#include <math.h>
#include <stdint.h>

#define BB 2
#define TT 2048
#define NH 16
#define HD 64
#define DD 1024
#define D3 3072
#define BT 4096   // BB*TT

// ---------------------------------------------------------------------------
// Scratch (no allocations allowed)
// ---------------------------------------------------------------------------
__device__ float g_qkv[(size_t)BT * D3];
__device__ __half g_x_hi [(size_t)BT * DD];
__device__ __half g_x_lo [(size_t)BT * DD];
__device__ __half g_c_hi [(size_t)BT * DD];
__device__ __half g_c_lo [(size_t)BT * DD];
__device__ __half g_q_hi [(size_t)BT * DD];
__device__ __half g_q_lo [(size_t)BT * DD];
__device__ __half g_k_hi [(size_t)BT * DD];
__device__ __half g_v_hi [(size_t)BT * DD];
__device__ __half g_wq_h [(size_t)D3 * DD];   // Wqkv^T fp16
__device__ __half g_wo_h [(size_t)DD * DD];   // Wout^T fp16

// ---------------------------------------------------------------------------
__device__ __forceinline__ uint32_t smem_u32(const void* p) {
    uint32_t a;
    asm("{ .reg .u64 t; cvta.to.shared.u64 t, %1; cvt.u32.u64 %0, t; }"
        : "=r"(a) : "l"(p));
    return a;
}
__device__ __forceinline__ void cp16(uint32_t dst, const void* src) {
    asm volatile("cp.async.ca.shared.global [%0], [%1], 16;" :: "r"(dst), "l"(src));
}
__device__ __forceinline__ void cp_commit() {
    asm volatile("cp.async.commit_group;" ::: "memory");
}
__device__ __forceinline__ void cp_wait0() {
    asm volatile("cp.async.wait_group 0;" ::: "memory");
}
__device__ __forceinline__ void cp_wait1() {
    asm volatile("cp.async.wait_group 1;" ::: "memory");
}
__device__ __forceinline__ void ldm_x4(uint32_t* r, uint32_t addr) {
    asm volatile("ldmatrix.sync.aligned.m8n8.x4.shared.b16 {%0,%1,%2,%3}, [%4];"
                 : "=r"(r[0]), "=r"(r[1]), "=r"(r[2]), "=r"(r[3]) : "r"(addr));
}
__device__ __forceinline__ void ldm_x4t(uint32_t* r, uint32_t addr) {
    asm volatile("ldmatrix.sync.aligned.m8n8.x4.trans.shared.b16 {%0,%1,%2,%3}, [%4];"
                 : "=r"(r[0]), "=r"(r[1]), "=r"(r[2]), "=r"(r[3]) : "r"(addr));
}
__device__ __forceinline__ void mma16816(float* c, const uint32_t* a, const uint32_t* b) {
    asm volatile(
        "mma.sync.aligned.m16n8k16.row.col.f32.f16.f16.f32 "
        "{%0,%1,%2,%3}, {%4,%5,%6,%7}, {%8,%9}, {%0,%1,%2,%3};"
        : "+f"(c[0]), "+f"(c[1]), "+f"(c[2]), "+f"(c[3])
        : "r"(a[0]), "r"(a[1]), "r"(a[2]), "r"(a[3]), "r"(b[0]), "r"(b[1]));
}
// split pair (a,b) into fp16x2 hi + fp16x2 residual-lo (a in low half)
__device__ __forceinline__ void split2h(float a, float b, uint32_t& hi, uint32_t& lo) {
    __half2 h = __floats2half2_rn(a, b);
    hi = *(uint32_t*)&h;
    float ra = a - __half2float(__low2half(h));
    float rb = b - __half2float(__high2half(h));
    __half2 l = __floats2half2_rn(ra, rb);
    lo = *(uint32_t*)&l;
}
// Conflict-free tile offset: 128 rows x 32 k fp16, row pairs packed in 128B
__device__ __forceinline__ uint32_t toff(int row, int c) {
    const int phys = row >> 1;
    const int unit = ((row & 1) * 4 + c) ^ (phys & 3);
    return (uint32_t)(phys * 128 + unit * 16);
}

// ---------------------------------------------------------------------------
// Elementwise fp32 -> fp16 hi/lo split
// ---------------------------------------------------------------------------
__global__ __launch_bounds__(256) void split_fp16(
    const float* __restrict__ src, __half* __restrict__ hi,
    __half* __restrict__ lo, int n4)
{
    int i = blockIdx.x * blockDim.x + threadIdx.x;
    if (i >= n4) return;
    float4 v = *(const float4*)(src + (size_t)i * 4);
    uint32_t h[2], l[2];
    split2h(v.x, v.y, h[0], l[0]);
    split2h(v.z, v.w, h[1], l[1]);
    *(uint64_t*)(hi + (size_t)i * 4) = *(uint64_t*)h;
    *(uint64_t*)(lo + (size_t)i * 4) = *(uint64_t*)l;
}

// ---------------------------------------------------------------------------
// Transpose + fp16 convert: W[K][N] -> Wt[N][K] fp16 (single)
// ---------------------------------------------------------------------------
__global__ __launch_bounds__(256) void transpose_fp16(
    const float* __restrict__ W, __half* __restrict__ Wt, int K, int N)
{
    __shared__ float t[32][33];
    const int nb = blockIdx.x * 32, kb = blockIdx.y * 32;
    const int tx = threadIdx.x & 31, ty0 = threadIdx.x >> 5;
#pragma unroll
    for (int i = 0; i < 4; i++) {
        int row = ty0 + i * 8;
        t[row][tx] = W[(size_t)(kb + row) * N + nb + tx];
    }
    __syncthreads();
#pragma unroll
    for (int i = 0; i < 4; i++) {
        int row = ty0 + i * 8;
        Wt[(size_t)(nb + row) * K + kb + tx] = __float2half_rn(t[tx][row]);
    }
}

// ---------------------------------------------------------------------------
// fp16 2-term GEMM via mma.sync: C = A(hi+lo) @ Bt(fp16)^T + bias
// 128x128 CTA tile, BK=32, 2-stage cp.async, 8 warps, 64x32 warp tile.
// ---------------------------------------------------------------------------
#define GSMEM (2 * 24576)

__global__ __launch_bounds__(256, 2) void gemm_fp16(
    const __half* __restrict__ Ahi, const __half* __restrict__ Alo,
    const __half* __restrict__ Bh,
    const float* __restrict__ bias, float* __restrict__ C,
    int M, int N, int K)
{
    extern __shared__ char sm[];
    const uint32_t sB = smem_u32(sm);
    const int tid = threadIdx.x, wid = tid >> 5, lane = tid & 31;
    const int bn = blockIdx.x, bm = blockIdx.y;
    const int wm = wid & 1, wn = wid >> 1;
    const int NC = K >> 5;

    const __half* gbase[3];
    gbase[0] = Ahi + (size_t)bm * 128 * K;
    gbase[1] = Alo + (size_t)bm * 128 * K;
    gbase[2] = Bh + (size_t)bn * 128 * K;

    auto load_chunk = [&](int c, int s) {
#pragma unroll
        for (int t = 0; t < 6; t++) {
            int id = tid + t * 256;           // 0..1535
            int tile = id >> 9;               // 0..2
            int rem = id & 511;
            int row = rem >> 2, ch = rem & 3;
            const __half* src = gbase[tile] + (size_t)row * K + c * 32 + ch * 8;
            uint32_t dst = sB + s * 24576 + tile * 8192 + toff(row, ch);
            cp16(dst, src);
        }
    };

    float acc[4][4][4];
#pragma unroll
    for (int i = 0; i < 4; i++)
#pragma unroll
        for (int j = 0; j < 4; j++)
#pragma unroll
            for (int k = 0; k < 4; k++) acc[i][j][k] = 0.f;

    const int l15 = lane & 15, lhi = lane >> 4;
    const int b7 = lane & 7, bK = (lane >> 3) & 1;

    uint32_t aOffH[2][4], bOffH[2][2];
#pragma unroll
    for (int ks = 0; ks < 2; ks++) {
#pragma unroll
        for (int mt = 0; mt < 4; mt++)
            aOffH[ks][mt] = toff(wm * 64 + mt * 16 + l15, ks * 2 + lhi);
#pragma unroll
        for (int p = 0; p < 2; p++)
            bOffH[ks][p] = toff(wn * 32 + (2 * p + lhi) * 8 + b7, ks * 2 + bK);
    }

    load_chunk(0, 0);
    cp_commit();

    for (int c = 0; c < NC; c++) {
        const int s = c & 1;
        if (c + 1 < NC) {
            load_chunk(c + 1, s ^ 1);
            cp_commit();
            cp_wait1();
        } else {
            cp_wait0();
        }
        __syncthreads();

        const uint32_t base = sB + s * 24576;
        const uint32_t aHiT = base, aLoT = base + 8192, bHT = base + 16384;

#pragma unroll
        for (int ks = 0; ks < 2; ks++) {
            uint32_t aF[4][4], bF[4][2];
#pragma unroll
            for (int mt = 0; mt < 4; mt++) ldm_x4(aF[mt], aHiT + aOffH[ks][mt]);
#pragma unroll
            for (int p = 0; p < 2; p++) {
                uint32_t t4[4];
                ldm_x4(t4, bHT + bOffH[ks][p]);
                bF[2 * p][0] = t4[0]; bF[2 * p][1] = t4[1];
                bF[2 * p + 1][0] = t4[2]; bF[2 * p + 1][1] = t4[3];
            }
#pragma unroll
            for (int mt = 0; mt < 4; mt++)
#pragma unroll
                for (int nt = 0; nt < 4; nt++)
                    mma16816(acc[mt][nt], aF[mt], bF[nt]);
#pragma unroll
            for (int mt = 0; mt < 4; mt++) ldm_x4(aF[mt], aLoT + aOffH[ks][mt]);
#pragma unroll
            for (int mt = 0; mt < 4; mt++)
#pragma unroll
                for (int nt = 0; nt < 4; nt++)
                    mma16816(acc[mt][nt], aF[mt], bF[nt]);
        }
        __syncthreads();
    }

    const int g = lane >> 2, tg2 = (lane & 3) * 2;
#pragma unroll
    for (int nt = 0; nt < 4; nt++) {
        const int col = bn * 128 + wn * 32 + nt * 8 + tg2;
        const float b0 = bias[col], b1 = bias[col + 1];
#pragma unroll
        for (int mt = 0; mt < 4; mt++) {
            const int r0 = bm * 128 + wm * 64 + mt * 16 + g;
            float2 v0 = make_float2(acc[mt][nt][0] + b0, acc[mt][nt][1] + b1);
            float2 v1 = make_float2(acc[mt][nt][2] + b0, acc[mt][nt][3] + b1);
            *(float2*)(C + (size_t)r0 * N + col) = v0;
            *(float2*)(C + (size_t)(r0 + 8) * N + col) = v1;
        }
    }
}

// ---------------------------------------------------------------------------
// RoPE + scatter + fp16 pre-split: q (x0.125) -> hi/lo, k -> fp16 + cache,
// v -> fp16 + cache.
// ---------------------------------------------------------------------------
__global__ __launch_bounds__(256) void rope_scatter(
    const float* __restrict__ qkv, float* __restrict__ cache,
    __half* __restrict__ qh, __half* __restrict__ ql,
    __half* __restrict__ kh, __half* __restrict__ vh,
    const int* __restrict__ offp)
{
    int idx = blockIdx.x * blockDim.x + threadIdx.x;
    int i = idx & 31;
    int h = (idx >> 5) & 15;
    int t = (idx >> 9) & (TT - 1);
    int b = idx >> 20;
    int off = offp ? offp[0] : 0;

    float inv_freq = exp2f(-(float)(2 * i) * (0.015625f * 13.287712379549449f));
    float ang = (float)(t + off) * inv_freq;
    float s, c;
    sincosf(ang, &s, &c);

    size_t base = ((size_t)(b * TT + t)) * D3 + h * HD + 2 * i;
    size_t eo = ((size_t)(b * TT + t)) * DD + h * HD + 2 * i;

    float q1 = qkv[base], q2 = qkv[base + 1];
    float qr1 = (q1 * c - q2 * s) * 0.125f;
    float qr2 = (q1 * s + q2 * c) * 0.125f;
    uint32_t hi, lo;
    split2h(qr1, qr2, hi, lo);
    *(uint32_t*)(qh + eo) = hi;
    *(uint32_t*)(ql + eo) = lo;

    float k1 = qkv[base + DD], k2 = qkv[base + DD + 1];
    float kr1 = k1 * c - k2 * s;
    float kr2 = k1 * s + k2 * c;
    size_t ko = ((size_t)((b * 2 + 0) * TT + t)) * DD + h * HD + 2 * i;
    cache[ko] = kr1;
    cache[ko + 1] = kr2;
    __half2 kp = __floats2half2_rn(kr1, kr2);
    *(uint32_t*)(kh + eo) = *(uint32_t*)&kp;

    float v1 = qkv[base + 2 * DD], v2 = qkv[base + 2 * DD + 1];
    size_t vo = ((size_t)((b * 2 + 1) * TT + t)) * DD + h * HD + 2 * i;
    cache[vo] = v1;
    cache[vo + 1] = v2;
    __half2 vp = __floats2half2_rn(v1, v2);
    *(uint32_t*)(vh + eo) = *(uint32_t*)&vp;
}

// ---------------------------------------------------------------------------
// Tensor-core flash attention, fp16 2-term (Q split, K single; P split,
// V single). BM=128 (8 warps x 16 rows), BN=64, pitch 72, double-buffered KV.
// ---------------------------------------------------------------------------
#define APITCH 72
#define QREG  (128 * APITCH * 2)       // 18432 bytes per Q array
#define KVARR (64 * APITCH * 2)        // 9216 bytes per KV array
#define KVST  (2 * KVARR)              // stage = KH,VH = 18432
#define ATT_SMEM (2 * QREG + 2 * KVST) // 73728

__global__ __launch_bounds__(256, 2) void attn_mma(
    const __half* __restrict__ qh, const __half* __restrict__ ql,
    const __half* __restrict__ kh, const __half* __restrict__ vh,
    __half* __restrict__ ch, __half* __restrict__ cl)
{
    extern __shared__ char smc[];
    const uint32_t sbase = smem_u32(smc);
    const uint32_t sQH = sbase, sQL = sbase + QREG;

    const int tid = threadIdx.x, wid = tid >> 5, lane = tid & 31;
    const int px = blockIdx.x, bh = blockIdx.y;
    const int b = bh >> 4, h = bh & 15;
    const int l15 = lane & 15, lhi = lane >> 4;
    const int g = lane >> 2, tg2 = (lane & 3) * 2;
    const int b7 = lane & 7, bK = (lane >> 3) & 1;

    const size_t hoff = ((size_t)(b * TT)) * DD + h * HD;
    const __half* qhb = qh + hoff;
    const __half* qlb = ql + hoff;
    const __half* srcs[2] = {kh + hoff, vh + hoff};

    auto load_q = [&](int mblk) {
#pragma unroll
        for (int t = 0; t < 8; t++) {
            int id = tid + t * 256;
            int arr = id >> 10;
            int rem = id & 1023;
            int r = rem >> 3, chk = rem & 7;
            const __half* src =
                (arr ? qlb : qhb) + (size_t)(mblk * 128 + r) * DD + chk * 8;
            uint32_t dst = (arr ? sQL : sQH) + r * 144 + chk * 16;
            cp16(dst, src);
        }
    };
    auto load_kv = [&](int kb, int stg) {
        const uint32_t kvb = sbase + 2 * QREG + stg * KVST;
#pragma unroll
        for (int t = 0; t < 4; t++) {
            int id = tid + t * 256;           // 0..1023
            int arr = id >> 9;                // 0..1
            int rem = id & 511;
            int r = rem >> 3, chk = rem & 7;
            const __half* src = srcs[arr] + (size_t)(kb * 64 + r) * DD + chk * 8;
            uint32_t dst = kvb + arr * KVARR + r * 144 + chk * 16;
            cp16(dst, src);
        }
    };

    for (int pass = 0; pass < 2; pass++) {
        const int mblk = pass ? (15 - px) : px;
        const int NKT = 2 * mblk + 2;

        __syncthreads();
        load_q(mblk);
        load_kv(0, 0);
        cp_commit();

        float o[8][4];
#pragma unroll
        for (int i = 0; i < 8; i++)
#pragma unroll
            for (int j = 0; j < 4; j++) o[i][j] = 0.f;
        float m0 = -1e30f, m1 = -1e30f, l0 = 0.f, l1 = 0.f;

        const int rowA = mblk * 128 + wid * 16 + g;
        const uint32_t aRowOff = (wid * 16 + l15) * 144;

        for (int kb = 0; kb < NKT; kb++) {
            const int stg = kb & 1;
            __syncthreads();
            if (kb + 1 < NKT) {
                load_kv(kb + 1, stg ^ 1);
                cp_commit();
                cp_wait1();
            } else {
                cp_wait0();
            }
            __syncthreads();

            const uint32_t kvb = sbase + 2 * QREG + stg * KVST;
            const uint32_t sKH = kvb, sVH = kvb + KVARR;

            float s[8][4];
#pragma unroll
            for (int i = 0; i < 8; i++)
#pragma unroll
                for (int j = 0; j < 4; j++) s[i][j] = 0.f;

#pragma unroll
            for (int ks = 0; ks < 4; ks++) {
                const uint32_t ach = (uint32_t)((ks * 2 + lhi) << 4);
                uint32_t aH[4], aL[4];
                ldm_x4(aH, sQH + aRowOff + ach);
                ldm_x4(aL, sQL + aRowOff + ach);
                const uint32_t bch = (uint32_t)((ks * 2 + bK) << 4);
#pragma unroll
                for (int p = 0; p < 4; p++) {
                    const uint32_t bro = ((2 * p + lhi) * 8 + b7) * 144 + bch;
                    uint32_t tH[4];
                    ldm_x4(tH, sKH + bro);
                    mma16816(s[2 * p],     aH, &tH[0]);
                    mma16816(s[2 * p],     aL, &tH[0]);
                    mma16816(s[2 * p + 1], aH, &tH[2]);
                    mma16816(s[2 * p + 1], aL, &tH[2]);
                }
            }

            if (kb >= 2 * mblk) {
                const int cbase = kb * 64;
#pragma unroll
                for (int nt = 0; nt < 8; nt++) {
                    const int c0 = cbase + nt * 8 + tg2;
                    if (c0 > rowA)     s[nt][0] = -1e30f;
                    if (c0 + 1 > rowA) s[nt][1] = -1e30f;
                    if (c0 > rowA + 8)     s[nt][2] = -1e30f;
                    if (c0 + 1 > rowA + 8) s[nt][3] = -1e30f;
                }
            }

            float mx0 = -1e30f, mx1 = -1e30f;
#pragma unroll
            for (int nt = 0; nt < 8; nt++) {
                mx0 = fmaxf(mx0, fmaxf(s[nt][0], s[nt][1]));
                mx1 = fmaxf(mx1, fmaxf(s[nt][2], s[nt][3]));
            }
            mx0 = fmaxf(mx0, __shfl_xor_sync(0xffffffffu, mx0, 1));
            mx0 = fmaxf(mx0, __shfl_xor_sync(0xffffffffu, mx0, 2));
            mx1 = fmaxf(mx1, __shfl_xor_sync(0xffffffffu, mx1, 1));
            mx1 = fmaxf(mx1, __shfl_xor_sync(0xffffffffu, mx1, 2));
            const float mn0 = fmaxf(m0, mx0), mn1 = fmaxf(m1, mx1);
            const float al0 = __expf(m0 - mn0), al1 = __expf(m1 - mn1);
            m0 = mn0; m1 = mn1;
            float sum0 = 0.f, sum1 = 0.f;
#pragma unroll
            for (int nt = 0; nt < 8; nt++) {
                s[nt][0] = __expf(s[nt][0] - mn0);
                s[nt][1] = __expf(s[nt][1] - mn0);
                s[nt][2] = __expf(s[nt][2] - mn1);
                s[nt][3] = __expf(s[nt][3] - mn1);
                sum0 += s[nt][0] + s[nt][1];
                sum1 += s[nt][2] + s[nt][3];
            }
            sum0 += __shfl_xor_sync(0xffffffffu, sum0, 1);
            sum0 += __shfl_xor_sync(0xffffffffu, sum0, 2);
            sum1 += __shfl_xor_sync(0xffffffffu, sum1, 1);
            sum1 += __shfl_xor_sync(0xffffffffu, sum1, 2);
            l0 = l0 * al0 + sum0;
            l1 = l1 * al1 + sum1;
#pragma unroll
            for (int nt = 0; nt < 8; nt++) {
                o[nt][0] *= al0; o[nt][1] *= al0;
                o[nt][2] *= al1; o[nt][3] *= al1;
            }

#pragma unroll
            for (int kt = 0; kt < 4; kt++) {
                const int n0 = kt * 2, n1 = kt * 2 + 1;
                uint32_t pH[4], pL[4];
                split2h(s[n0][0], s[n0][1], pH[0], pL[0]);
                split2h(s[n0][2], s[n0][3], pH[1], pL[1]);
                split2h(s[n1][0], s[n1][1], pH[2], pL[2]);
                split2h(s[n1][2], s[n1][3], pH[3], pL[3]);
#pragma unroll
                for (int p = 0; p < 4; p++) {
                    const uint32_t va = (kt * 16 + l15) * 144 + (2 * p + lhi) * 16;
                    uint32_t tH[4];
                    ldm_x4t(tH, sVH + va);
                    mma16816(o[2 * p],     pH, &tH[0]);
                    mma16816(o[2 * p],     pL, &tH[0]);
                    mma16816(o[2 * p + 1], pH, &tH[2]);
                    mma16816(o[2 * p + 1], pL, &tH[2]);
                }
            }
        }

        // ---- finalize + fused fp16 hi/lo store ----
        const float inv0 = 1.f / l0, inv1 = 1.f / l1;
        __half* ch0 = ch + (size_t)(b * TT + rowA) * DD + h * HD;
        __half* cl0 = cl + (size_t)(b * TT + rowA) * DD + h * HD;
        __half* ch1 = ch0 + (size_t)8 * DD;
        __half* cl1 = cl0 + (size_t)8 * DD;
#pragma unroll
        for (int nt = 0; nt < 8; nt++) {
            uint32_t hi, lo;
            split2h(o[nt][0] * inv0, o[nt][1] * inv0, hi, lo);
            *(uint32_t*)(ch0 + nt * 8 + tg2) = hi;
            *(uint32_t*)(cl0 + nt * 8 + tg2) = lo;
            split2h(o[nt][2] * inv1, o[nt][3] * inv1, hi, lo);
            *(uint32_t*)(ch1 + nt * 8 + tg2) = hi;
            *(uint32_t*)(cl1 + nt * 8 + tg2) = lo;
        }
    }
}

// ---------------------------------------------------------------------------
extern "C" void kernel_launch(void* const* d_in, const int* in_sizes, int n_in,
                              void* d_out, int out_size)
{
    const float* x    = (const float*)d_in[0];
    const float* Wqkv = (const float*)d_in[1];
    const float* bqkv = (const float*)d_in[2];
    const float* Wout = (const float*)d_in[3];
    const float* bout = (const float*)d_in[4];
    const int*   offp = (n_in > 5) ? (const int*)d_in[5] : nullptr;

    float* out   = (float*)d_out;
    float* cache = out + (size_t)BT * DD;

    float *qkv;
    __half *xh, *xl, *ch, *cl, *wqh, *woh;
    __half *qh, *ql, *kh, *vh;
    cudaGetSymbolAddress((void**)&qkv,  g_qkv);
    cudaGetSymbolAddress((void**)&xh,   g_x_hi);
    cudaGetSymbolAddress((void**)&xl,   g_x_lo);
    cudaGetSymbolAddress((void**)&ch,   g_c_hi);
    cudaGetSymbolAddress((void**)&cl,   g_c_lo);
    cudaGetSymbolAddress((void**)&wqh,  g_wq_h);
    cudaGetSymbolAddress((void**)&woh,  g_wo_h);
    cudaGetSymbolAddress((void**)&qh,   g_q_hi);
    cudaGetSymbolAddress((void**)&ql,   g_q_lo);
    cudaGetSymbolAddress((void**)&kh,   g_k_hi);
    cudaGetSymbolAddress((void**)&vh,   g_v_hi);

    cudaFuncSetAttribute(gemm_fp16, cudaFuncAttributeMaxDynamicSharedMemorySize,
                         GSMEM);
    cudaFuncSetAttribute(attn_mma, cudaFuncAttributeMaxDynamicSharedMemorySize,
                         ATT_SMEM);

    // 0) input split + weight transpose/convert
    split_fp16<<<(BT * DD / 4) / 256, 256>>>(x, xh, xl, BT * DD / 4);
    transpose_fp16<<<dim3(D3 / 32, DD / 32), 256>>>(Wqkv, wqh, DD, D3);
    transpose_fp16<<<dim3(DD / 32, DD / 32), 256>>>(Wout, woh, DD, DD);

    // 1) QKV projection (fp16 2-term)
    gemm_fp16<<<dim3(D3 / 128, BT / 128), 256, GSMEM>>>(
        xh, xl, wqh, bqkv, qkv, BT, D3, DD);

    // 2) RoPE + scatter + fp16 pre-split
    rope_scatter<<<(BB * TT * NH * 32) / 256, 256>>>(
        qkv, cache, qh, ql, kh, vh, offp);

    // 3) Tensor-core causal flash attention (writes ctx as fp16 hi/lo)
    attn_mma<<<dim3(8, BB * NH), 256, ATT_SMEM>>>(
        qh, ql, kh, vh, ch, cl);

    // 4) Output projection (fp16 2-term)
    gemm_fp16<<<dim3(DD / 128, BT / 128), 256, GSMEM>>>(
        ch, cl, woh, bout, out, BT, DD, DD);
}

// round 16
// speedup vs baseline: 1.4237x; 1.0073x over previous
#include <cuda_runtime.h>
#include <cuda_fp16.h>
#include <math.h>
#include <stdint.h>

#define BB 2
#define TT 2048
#define NH 16
#define HD 64
#define DD 1024
#define D3 3072
#define BT 4096   // BB*TT

// ---------------------------------------------------------------------------
// Scratch (no allocations allowed)
// ---------------------------------------------------------------------------
__device__ float g_qkv[(size_t)BT * D3];
__device__ __half g_x_hi [(size_t)BT * DD];
__device__ __half g_x_lo [(size_t)BT * DD];
__device__ __half g_c_hi [(size_t)BT * DD];
__device__ __half g_c_lo [(size_t)BT * DD];
__device__ __half g_q_hi [(size_t)BT * DD];
__device__ __half g_q_lo [(size_t)BT * DD];
__device__ __half g_k_hi [(size_t)BT * DD];
__device__ __half g_v_hi [(size_t)BT * DD];
__device__ __half g_wq_h [(size_t)D3 * DD];   // Wqkv^T fp16
__device__ __half g_wo_h [(size_t)DD * DD];   // Wout^T fp16

// ---------------------------------------------------------------------------
__device__ __forceinline__ uint32_t smem_u32(const void* p) {
    uint32_t a;
    asm("{ .reg .u64 t; cvta.to.shared.u64 t, %1; cvt.u32.u64 %0, t; }"
        : "=r"(a) : "l"(p));
    return a;
}
__device__ __forceinline__ void cp16(uint32_t dst, const void* src) {
    asm volatile("cp.async.ca.shared.global [%0], [%1], 16;" :: "r"(dst), "l"(src));
}
__device__ __forceinline__ void cp_commit() {
    asm volatile("cp.async.commit_group;" ::: "memory");
}
__device__ __forceinline__ void cp_wait0() {
    asm volatile("cp.async.wait_group 0;" ::: "memory");
}
__device__ __forceinline__ void cp_wait1() {
    asm volatile("cp.async.wait_group 1;" ::: "memory");
}
__device__ __forceinline__ void ldm_x4(uint32_t* r, uint32_t addr) {
    asm volatile("ldmatrix.sync.aligned.m8n8.x4.shared.b16 {%0,%1,%2,%3}, [%4];"
                 : "=r"(r[0]), "=r"(r[1]), "=r"(r[2]), "=r"(r[3]) : "r"(addr));
}
__device__ __forceinline__ void ldm_x4t(uint32_t* r, uint32_t addr) {
    asm volatile("ldmatrix.sync.aligned.m8n8.x4.trans.shared.b16 {%0,%1,%2,%3}, [%4];"
                 : "=r"(r[0]), "=r"(r[1]), "=r"(r[2]), "=r"(r[3]) : "r"(addr));
}
__device__ __forceinline__ void mma16816(float* c, const uint32_t* a, const uint32_t* b) {
    asm volatile(
        "mma.sync.aligned.m16n8k16.row.col.f32.f16.f16.f32 "
        "{%0,%1,%2,%3}, {%4,%5,%6,%7}, {%8,%9}, {%0,%1,%2,%3};"
        : "+f"(c[0]), "+f"(c[1]), "+f"(c[2]), "+f"(c[3])
        : "r"(a[0]), "r"(a[1]), "r"(a[2]), "r"(a[3]), "r"(b[0]), "r"(b[1]));
}
// split pair (a,b) into fp16x2 hi + fp16x2 residual-lo (a in low half)
__device__ __forceinline__ void split2h(float a, float b, uint32_t& hi, uint32_t& lo) {
    __half2 h = __floats2half2_rn(a, b);
    hi = *(uint32_t*)&h;
    float ra = a - __half2float(__low2half(h));
    float rb = b - __half2float(__high2half(h));
    __half2 l = __floats2half2_rn(ra, rb);
    lo = *(uint32_t*)&l;
}
// Conflict-free tile offset: 128 rows x 32 k fp16, row pairs packed in 128B
__device__ __forceinline__ uint32_t toff(int row, int c) {
    const int phys = row >> 1;
    const int unit = ((row & 1) * 4 + c) ^ (phys & 3);
    return (uint32_t)(phys * 128 + unit * 16);
}

// ---------------------------------------------------------------------------
// Elementwise fp32 -> fp16 hi/lo split
// ---------------------------------------------------------------------------
__global__ __launch_bounds__(256) void split_fp16(
    const float* __restrict__ src, __half* __restrict__ hi,
    __half* __restrict__ lo, int n4)
{
    int i = blockIdx.x * blockDim.x + threadIdx.x;
    if (i >= n4) return;
    float4 v = *(const float4*)(src + (size_t)i * 4);
    uint32_t h[2], l[2];
    split2h(v.x, v.y, h[0], l[0]);
    split2h(v.z, v.w, h[1], l[1]);
    *(uint64_t*)(hi + (size_t)i * 4) = *(uint64_t*)h;
    *(uint64_t*)(lo + (size_t)i * 4) = *(uint64_t*)l;
}

// ---------------------------------------------------------------------------
// Transpose + fp16 convert: W[K][N] -> Wt[N][K] fp16 (single)
// ---------------------------------------------------------------------------
__global__ __launch_bounds__(256) void transpose_fp16(
    const float* __restrict__ W, __half* __restrict__ Wt, int K, int N)
{
    __shared__ float t[32][33];
    const int nb = blockIdx.x * 32, kb = blockIdx.y * 32;
    const int tx = threadIdx.x & 31, ty0 = threadIdx.x >> 5;
#pragma unroll
    for (int i = 0; i < 4; i++) {
        int row = ty0 + i * 8;
        t[row][tx] = W[(size_t)(kb + row) * N + nb + tx];
    }
    __syncthreads();
#pragma unroll
    for (int i = 0; i < 4; i++) {
        int row = ty0 + i * 8;
        Wt[(size_t)(nb + row) * K + kb + tx] = __float2half_rn(t[tx][row]);
    }
}

// ---------------------------------------------------------------------------
// fp16 2-term GEMM via mma.sync: C = A(hi+lo) @ Bt(fp16)^T + bias
// 128x128 CTA tile, BK=64 (two 32-k sub-chunks per sync round), 2-stage
// cp.async, 8 warps, 64x32 warp tile. Stage = 48KB, 2 stages = 96KB.
// ---------------------------------------------------------------------------
#define GSUB  24576
#define GSTG  (2 * GSUB)      // 49152
#define GSMEM (2 * GSTG)      // 98304

__global__ __launch_bounds__(256, 2) void gemm_fp16(
    const __half* __restrict__ Ahi, const __half* __restrict__ Alo,
    const __half* __restrict__ Bh,
    const float* __restrict__ bias, float* __restrict__ C,
    int M, int N, int K)
{
    extern __shared__ char sm[];
    const uint32_t sB = smem_u32(sm);
    const int tid = threadIdx.x, wid = tid >> 5, lane = tid & 31;
    const int bn = blockIdx.x, bm = blockIdx.y;
    const int wm = wid & 1, wn = wid >> 1;
    const int NC = K >> 6;    // 64-wide chunks

    const __half* gbase[3];
    gbase[0] = Ahi + (size_t)bm * 128 * K;
    gbase[1] = Alo + (size_t)bm * 128 * K;
    gbase[2] = Bh + (size_t)bn * 128 * K;

    // load one 64-k stage = two 32-k sub-chunks
    auto load_stage = [&](int c, int s) {
#pragma unroll
        for (int t = 0; t < 12; t++) {
            int id = tid + t * 256;           // 0..3071
            int sub = id >> 11;               // 0..1 (1536 per sub)
            int rem = id & 2047;
            if (rem >= 1536) { sub = 1; rem -= 1536; }
            // simpler exact mapping:
            int id2 = tid + t * 256;
            sub = (id2 >= 1536) ? 1 : 0;
            rem = id2 - sub * 1536;
            int tile = rem >> 9;              // 0..2
            int r2 = rem & 511;
            int row = r2 >> 2, ch = r2 & 3;
            const __half* src = gbase[tile] + (size_t)row * K + c * 64 + sub * 32 + ch * 8;
            uint32_t dst = sB + s * GSTG + sub * GSUB + tile * 8192 + toff(row, ch);
            cp16(dst, src);
        }
    };

    float acc[4][4][4];
#pragma unroll
    for (int i = 0; i < 4; i++)
#pragma unroll
        for (int j = 0; j < 4; j++)
#pragma unroll
            for (int k = 0; k < 4; k++) acc[i][j][k] = 0.f;

    const int l15 = lane & 15, lhi = lane >> 4;
    const int b7 = lane & 7, bK = (lane >> 3) & 1;

    uint32_t aOffH[2][4], bOffH[2][2];
#pragma unroll
    for (int ks = 0; ks < 2; ks++) {
#pragma unroll
        for (int mt = 0; mt < 4; mt++)
            aOffH[ks][mt] = toff(wm * 64 + mt * 16 + l15, ks * 2 + lhi);
#pragma unroll
        for (int p = 0; p < 2; p++)
            bOffH[ks][p] = toff(wn * 32 + (2 * p + lhi) * 8 + b7, ks * 2 + bK);
    }

    load_stage(0, 0);
    cp_commit();

    for (int c = 0; c < NC; c++) {
        const int s = c & 1;
        if (c + 1 < NC) {
            load_stage(c + 1, s ^ 1);
            cp_commit();
            cp_wait1();
        } else {
            cp_wait0();
        }
        __syncthreads();

#pragma unroll
        for (int sub = 0; sub < 2; sub++) {
            const uint32_t base = sB + s * GSTG + sub * GSUB;
            const uint32_t aHiT = base, aLoT = base + 8192, bHT = base + 16384;

#pragma unroll
            for (int ks = 0; ks < 2; ks++) {
                uint32_t aF[4][4], bF[4][2];
#pragma unroll
                for (int mt = 0; mt < 4; mt++) ldm_x4(aF[mt], aHiT + aOffH[ks][mt]);
#pragma unroll
                for (int p = 0; p < 2; p++) {
                    uint32_t t4[4];
                    ldm_x4(t4, bHT + bOffH[ks][p]);
                    bF[2 * p][0] = t4[0]; bF[2 * p][1] = t4[1];
                    bF[2 * p + 1][0] = t4[2]; bF[2 * p + 1][1] = t4[3];
                }
#pragma unroll
                for (int mt = 0; mt < 4; mt++)
#pragma unroll
                    for (int nt = 0; nt < 4; nt++)
                        mma16816(acc[mt][nt], aF[mt], bF[nt]);
#pragma unroll
                for (int mt = 0; mt < 4; mt++) ldm_x4(aF[mt], aLoT + aOffH[ks][mt]);
#pragma unroll
                for (int mt = 0; mt < 4; mt++)
#pragma unroll
                    for (int nt = 0; nt < 4; nt++)
                        mma16816(acc[mt][nt], aF[mt], bF[nt]);
            }
        }
        __syncthreads();
    }

    const int g = lane >> 2, tg2 = (lane & 3) * 2;
#pragma unroll
    for (int nt = 0; nt < 4; nt++) {
        const int col = bn * 128 + wn * 32 + nt * 8 + tg2;
        const float b0 = bias[col], b1 = bias[col + 1];
#pragma unroll
        for (int mt = 0; mt < 4; mt++) {
            const int r0 = bm * 128 + wm * 64 + mt * 16 + g;
            float2 v0 = make_float2(acc[mt][nt][0] + b0, acc[mt][nt][1] + b1);
            float2 v1 = make_float2(acc[mt][nt][2] + b0, acc[mt][nt][3] + b1);
            *(float2*)(C + (size_t)r0 * N + col) = v0;
            *(float2*)(C + (size_t)(r0 + 8) * N + col) = v1;
        }
    }
}

// ---------------------------------------------------------------------------
// RoPE + scatter + fp16 pre-split: q (x0.125) -> hi/lo, k -> fp16 + cache,
// v -> fp16 + cache.
// ---------------------------------------------------------------------------
__global__ __launch_bounds__(256) void rope_scatter(
    const float* __restrict__ qkv, float* __restrict__ cache,
    __half* __restrict__ qh, __half* __restrict__ ql,
    __half* __restrict__ kh, __half* __restrict__ vh,
    const int* __restrict__ offp)
{
    int idx = blockIdx.x * blockDim.x + threadIdx.x;
    int i = idx & 31;
    int h = (idx >> 5) & 15;
    int t = (idx >> 9) & (TT - 1);
    int b = idx >> 20;
    int off = offp ? offp[0] : 0;

    float inv_freq = exp2f(-(float)(2 * i) * (0.015625f * 13.287712379549449f));
    float ang = (float)(t + off) * inv_freq;
    float s, c;
    sincosf(ang, &s, &c);

    size_t base = ((size_t)(b * TT + t)) * D3 + h * HD + 2 * i;
    size_t eo = ((size_t)(b * TT + t)) * DD + h * HD + 2 * i;

    float q1 = qkv[base], q2 = qkv[base + 1];
    float qr1 = (q1 * c - q2 * s) * 0.125f;
    float qr2 = (q1 * s + q2 * c) * 0.125f;
    uint32_t hi, lo;
    split2h(qr1, qr2, hi, lo);
    *(uint32_t*)(qh + eo) = hi;
    *(uint32_t*)(ql + eo) = lo;

    float k1 = qkv[base + DD], k2 = qkv[base + DD + 1];
    float kr1 = k1 * c - k2 * s;
    float kr2 = k1 * s + k2 * c;
    size_t ko = ((size_t)((b * 2 + 0) * TT + t)) * DD + h * HD + 2 * i;
    cache[ko] = kr1;
    cache[ko + 1] = kr2;
    __half2 kp = __floats2half2_rn(kr1, kr2);
    *(uint32_t*)(kh + eo) = *(uint32_t*)&kp;

    float v1 = qkv[base + 2 * DD], v2 = qkv[base + 2 * DD + 1];
    size_t vo = ((size_t)((b * 2 + 1) * TT + t)) * DD + h * HD + 2 * i;
    cache[vo] = v1;
    cache[vo + 1] = v2;
    __half2 vp = __floats2half2_rn(v1, v2);
    *(uint32_t*)(vh + eo) = *(uint32_t*)&vp;
}

// ---------------------------------------------------------------------------
// Tensor-core flash attention, fp16 2-term (Q split, K single; P split,
// V single). BM=128 (8 warps x 16 rows), BN=64, pitch 72, double-buffered KV.
// ---------------------------------------------------------------------------
#define APITCH 72
#define QREG  (128 * APITCH * 2)       // 18432 bytes per Q array
#define KVARR (64 * APITCH * 2)        // 9216 bytes per KV array
#define KVST  (2 * KVARR)              // stage = KH,VH = 18432
#define ATT_SMEM (2 * QREG + 2 * KVST) // 73728

__global__ __launch_bounds__(256, 2) void attn_mma(
    const __half* __restrict__ qh, const __half* __restrict__ ql,
    const __half* __restrict__ kh, const __half* __restrict__ vh,
    __half* __restrict__ ch, __half* __restrict__ cl)
{
    extern __shared__ char smc[];
    const uint32_t sbase = smem_u32(smc);
    const uint32_t sQH = sbase, sQL = sbase + QREG;

    const int tid = threadIdx.x, wid = tid >> 5, lane = tid & 31;
    const int px = blockIdx.x, bh = blockIdx.y;
    const int b = bh >> 4, h = bh & 15;
    const int l15 = lane & 15, lhi = lane >> 4;
    const int g = lane >> 2, tg2 = (lane & 3) * 2;
    const int b7 = lane & 7, bK = (lane >> 3) & 1;

    const size_t hoff = ((size_t)(b * TT)) * DD + h * HD;
    const __half* qhb = qh + hoff;
    const __half* qlb = ql + hoff;
    const __half* srcs[2] = {kh + hoff, vh + hoff};

    auto load_q = [&](int mblk) {
#pragma unroll
        for (int t = 0; t < 8; t++) {
            int id = tid + t * 256;
            int arr = id >> 10;
            int rem = id & 1023;
            int r = rem >> 3, chk = rem & 7;
            const __half* src =
                (arr ? qlb : qhb) + (size_t)(mblk * 128 + r) * DD + chk * 8;
            uint32_t dst = (arr ? sQL : sQH) + r * 144 + chk * 16;
            cp16(dst, src);
        }
    };
    auto load_kv = [&](int kb, int stg) {
        const uint32_t kvb = sbase + 2 * QREG + stg * KVST;
#pragma unroll
        for (int t = 0; t < 4; t++) {
            int id = tid + t * 256;           // 0..1023
            int arr = id >> 9;                // 0..1
            int rem = id & 511;
            int r = rem >> 3, chk = rem & 7;
            const __half* src = srcs[arr] + (size_t)(kb * 64 + r) * DD + chk * 8;
            uint32_t dst = kvb + arr * KVARR + r * 144 + chk * 16;
            cp16(dst, src);
        }
    };

    for (int pass = 0; pass < 2; pass++) {
        const int mblk = pass ? (15 - px) : px;
        const int NKT = 2 * mblk + 2;

        __syncthreads();
        load_q(mblk);
        load_kv(0, 0);
        cp_commit();

        float o[8][4];
#pragma unroll
        for (int i = 0; i < 8; i++)
#pragma unroll
            for (int j = 0; j < 4; j++) o[i][j] = 0.f;
        float m0 = -1e30f, m1 = -1e30f, l0 = 0.f, l1 = 0.f;

        const int rowA = mblk * 128 + wid * 16 + g;
        const uint32_t aRowOff = (wid * 16 + l15) * 144;

        for (int kb = 0; kb < NKT; kb++) {
            const int stg = kb & 1;
            __syncthreads();
            if (kb + 1 < NKT) {
                load_kv(kb + 1, stg ^ 1);
                cp_commit();
                cp_wait1();
            } else {
                cp_wait0();
            }
            __syncthreads();

            const uint32_t kvb = sbase + 2 * QREG + stg * KVST;
            const uint32_t sKH = kvb, sVH = kvb + KVARR;

            float s[8][4];
#pragma unroll
            for (int i = 0; i < 8; i++)
#pragma unroll
                for (int j = 0; j < 4; j++) s[i][j] = 0.f;

#pragma unroll
            for (int ks = 0; ks < 4; ks++) {
                const uint32_t ach = (uint32_t)((ks * 2 + lhi) << 4);
                uint32_t aH[4], aL[4];
                ldm_x4(aH, sQH + aRowOff + ach);
                ldm_x4(aL, sQL + aRowOff + ach);
                const uint32_t bch = (uint32_t)((ks * 2 + bK) << 4);
#pragma unroll
                for (int p = 0; p < 4; p++) {
                    const uint32_t bro = ((2 * p + lhi) * 8 + b7) * 144 + bch;
                    uint32_t tH[4];
                    ldm_x4(tH, sKH + bro);
                    mma16816(s[2 * p],     aH, &tH[0]);
                    mma16816(s[2 * p],     aL, &tH[0]);
                    mma16816(s[2 * p + 1], aH, &tH[2]);
                    mma16816(s[2 * p + 1], aL, &tH[2]);
                }
            }

            if (kb >= 2 * mblk) {
                const int cbase = kb * 64;
#pragma unroll
                for (int nt = 0; nt < 8; nt++) {
                    const int c0 = cbase + nt * 8 + tg2;
                    if (c0 > rowA)     s[nt][0] = -1e30f;
                    if (c0 + 1 > rowA) s[nt][1] = -1e30f;
                    if (c0 > rowA + 8)     s[nt][2] = -1e30f;
                    if (c0 + 1 > rowA + 8) s[nt][3] = -1e30f;
                }
            }

            float mx0 = -1e30f, mx1 = -1e30f;
#pragma unroll
            for (int nt = 0; nt < 8; nt++) {
                mx0 = fmaxf(mx0, fmaxf(s[nt][0], s[nt][1]));
                mx1 = fmaxf(mx1, fmaxf(s[nt][2], s[nt][3]));
            }
            mx0 = fmaxf(mx0, __shfl_xor_sync(0xffffffffu, mx0, 1));
            mx0 = fmaxf(mx0, __shfl_xor_sync(0xffffffffu, mx0, 2));
            mx1 = fmaxf(mx1, __shfl_xor_sync(0xffffffffu, mx1, 1));
            mx1 = fmaxf(mx1, __shfl_xor_sync(0xffffffffu, mx1, 2));
            const float mn0 = fmaxf(m0, mx0), mn1 = fmaxf(m1, mx1);
            const float al0 = __expf(m0 - mn0), al1 = __expf(m1 - mn1);
            m0 = mn0; m1 = mn1;
            float sum0 = 0.f, sum1 = 0.f;
#pragma unroll
            for (int nt = 0; nt < 8; nt++) {
                s[nt][0] = __expf(s[nt][0] - mn0);
                s[nt][1] = __expf(s[nt][1] - mn0);
                s[nt][2] = __expf(s[nt][2] - mn1);
                s[nt][3] = __expf(s[nt][3] - mn1);
                sum0 += s[nt][0] + s[nt][1];
                sum1 += s[nt][2] + s[nt][3];
            }
            sum0 += __shfl_xor_sync(0xffffffffu, sum0, 1);
            sum0 += __shfl_xor_sync(0xffffffffu, sum0, 2);
            sum1 += __shfl_xor_sync(0xffffffffu, sum1, 1);
            sum1 += __shfl_xor_sync(0xffffffffu, sum1, 2);
            l0 = l0 * al0 + sum0;
            l1 = l1 * al1 + sum1;
#pragma unroll
            for (int nt = 0; nt < 8; nt++) {
                o[nt][0] *= al0; o[nt][1] *= al0;
                o[nt][2] *= al1; o[nt][3] *= al1;
            }

#pragma unroll
            for (int kt = 0; kt < 4; kt++) {
                const int n0 = kt * 2, n1 = kt * 2 + 1;
                uint32_t pH[4], pL[4];
                split2h(s[n0][0], s[n0][1], pH[0], pL[0]);
                split2h(s[n0][2], s[n0][3], pH[1], pL[1]);
                split2h(s[n1][0], s[n1][1], pH[2], pL[2]);
                split2h(s[n1][2], s[n1][3], pH[3], pL[3]);
#pragma unroll
                for (int p = 0; p < 4; p++) {
                    const uint32_t va = (kt * 16 + l15) * 144 + (2 * p + lhi) * 16;
                    uint32_t tH[4];
                    ldm_x4t(tH, sVH + va);
                    mma16816(o[2 * p],     pH, &tH[0]);
                    mma16816(o[2 * p],     pL, &tH[0]);
                    mma16816(o[2 * p + 1], pH, &tH[2]);
                    mma16816(o[2 * p + 1], pL, &tH[2]);
                }
            }
        }

        // ---- finalize + fused fp16 hi/lo store ----
        const float inv0 = 1.f / l0, inv1 = 1.f / l1;
        __half* ch0 = ch + (size_t)(b * TT + rowA) * DD + h * HD;
        __half* cl0 = cl + (size_t)(b * TT + rowA) * DD + h * HD;
        __half* ch1 = ch0 + (size_t)8 * DD;
        __half* cl1 = cl0 + (size_t)8 * DD;
#pragma unroll
        for (int nt = 0; nt < 8; nt++) {
            uint32_t hi, lo;
            split2h(o[nt][0] * inv0, o[nt][1] * inv0, hi, lo);
            *(uint32_t*)(ch0 + nt * 8 + tg2) = hi;
            *(uint32_t*)(cl0 + nt * 8 + tg2) = lo;
            split2h(o[nt][2] * inv1, o[nt][3] * inv1, hi, lo);
            *(uint32_t*)(ch1 + nt * 8 + tg2) = hi;
            *(uint32_t*)(cl1 + nt * 8 + tg2) = lo;
        }
    }
}

// ---------------------------------------------------------------------------
extern "C" void kernel_launch(void* const* d_in, const int* in_sizes, int n_in,
                              void* d_out, int out_size)
{
    const float* x    = (const float*)d_in[0];
    const float* Wqkv = (const float*)d_in[1];
    const float* bqkv = (const float*)d_in[2];
    const float* Wout = (const float*)d_in[3];
    const float* bout = (const float*)d_in[4];
    const int*   offp = (n_in > 5) ? (const int*)d_in[5] : nullptr;

    float* out   = (float*)d_out;
    float* cache = out + (size_t)BT * DD;

    float *qkv;
    __half *xh, *xl, *ch, *cl, *wqh, *woh;
    __half *qh, *ql, *kh, *vh;
    cudaGetSymbolAddress((void**)&qkv,  g_qkv);
    cudaGetSymbolAddress((void**)&xh,   g_x_hi);
    cudaGetSymbolAddress((void**)&xl,   g_x_lo);
    cudaGetSymbolAddress((void**)&ch,   g_c_hi);
    cudaGetSymbolAddress((void**)&cl,   g_c_lo);
    cudaGetSymbolAddress((void**)&wqh,  g_wq_h);
    cudaGetSymbolAddress((void**)&woh,  g_wo_h);
    cudaGetSymbolAddress((void**)&qh,   g_q_hi);
    cudaGetSymbolAddress((void**)&ql,   g_q_lo);
    cudaGetSymbolAddress((void**)&kh,   g_k_hi);
    cudaGetSymbolAddress((void**)&vh,   g_v_hi);

    cudaFuncSetAttribute(gemm_fp16, cudaFuncAttributeMaxDynamicSharedMemorySize,
                         GSMEM);
    cudaFuncSetAttribute(attn_mma, cudaFuncAttributeMaxDynamicSharedMemorySize,
                         ATT_SMEM);

    // 0) input split + weight transpose/convert
    split_fp16<<<(BT * DD / 4) / 256, 256>>>(x, xh, xl, BT * DD / 4);
    transpose_fp16<<<dim3(D3 / 32, DD / 32), 256>>>(Wqkv, wqh, DD, D3);
    transpose_fp16<<<dim3(DD / 32, DD / 32), 256>>>(Wout, woh, DD, DD);

    // 1) QKV projection (fp16 2-term, BK=64)
    gemm_fp16<<<dim3(D3 / 128, BT / 128), 256, GSMEM>>>(
        xh, xl, wqh, bqkv, qkv, BT, D3, DD);

    // 2) RoPE + scatter + fp16 pre-split
    rope_scatter<<<(BB * TT * NH * 32) / 256, 256>>>(
        qkv, cache, qh, ql, kh, vh, offp);

    // 3) Tensor-core causal flash attention (writes ctx as fp16 hi/lo)
    attn_mma<<<dim3(8, BB * NH), 256, ATT_SMEM>>>(
        qh, ql, kh, vh, ch, cl);

    // 4) Output projection (fp16 2-term, BK=64)
    gemm_fp16<<<dim3(DD / 128, BT / 128), 256, GSMEM>>>(
        ch, cl, woh, bout, out, BT, DD, DD);
}